// round 2
// baseline (speedup 1.0000x reference)
#include <cuda_runtime.h>
#include <math_constants.h>
#include <stdint.h>

#define CCH 256               // channels
#define NLEV 4

// Transposed scratch (HW, C) for all 4 pyramid levels, fp32.
// 65536*256 + 16384*256 + 4096*256 + 1024*256 = 22282240 floats (89.1 MB)
__device__ __align__(16) float g_featT[22282240];

// ---------------------------------------------------------------------------
// Fused transpose: (C, HW) -> (HW, C) for all 4 levels in one launch.
// blockIdx.z = level; 32x32 smem tile, conflict-free, coalesced both ways.
// ---------------------------------------------------------------------------
__global__ void transpose_all(const float* __restrict__ p2,
                              const float* __restrict__ p3,
                              const float* __restrict__ p4,
                              const float* __restrict__ p5) {
    const int l = blockIdx.z;
    const int HWs[NLEV]      = {65536, 16384, 4096, 1024};
    const size_t offs[NLEV]  = {0, 16777216, 16777216 + 4194304,
                                16777216 + 4194304 + 1048576};
    const int HW = HWs[l];
    if ((int)blockIdx.x * 32 >= HW) return;

    const float* __restrict__ in = (l == 0) ? p2 : (l == 1) ? p3
                                  : (l == 2) ? p4 : p5;
    const size_t out_off = offs[l];

    __shared__ float tile[32][33];
    const int tx = threadIdx.x;          // 0..31
    const int ty = threadIdx.y;          // 0..7
    const int x  = blockIdx.x * 32 + tx; // HW index (read phase)
    const int c0 = blockIdx.y * 32;      // channel tile base

#pragma unroll
    for (int j = 0; j < 32; j += 8) {
        tile[ty + j][tx] = in[(size_t)(c0 + ty + j) * HW + x];
    }
    __syncthreads();

    const int xo = blockIdx.x * 32 + ty; // HW index (write phase)
#pragma unroll
    for (int j = 0; j < 32; j += 8) {
        g_featT[out_off + (size_t)(xo + j) * CCH + (c0 + tx)] = tile[tx][ty + j];
    }
}

// ---------------------------------------------------------------------------
// ROIAlign main kernel. One block per proposal; 256 threads =
// 64 channel-groups (float4) x 4 pixel slices. Reads transposed features
// (HW, C): each corner fetch is 512B contiguous per warp.
// Output staged in shared memory, then flushed with a linear float4 copy
// (fully coalesced stores -> ~16x fewer store wavefronts than direct STG).
// ---------------------------------------------------------------------------
__global__ __launch_bounds__(256) void roialign_kernel(
    const float* __restrict__ proposals,
    float* __restrict__ out) {

    extern __shared__ float sOut[];   // 256*49 = 12544 floats = 50176 B

    const int n   = blockIdx.x;
    const int tid = threadIdx.x;
    const int g   = tid & 63;   // channel group -> channels 4g..4g+3
    const int p   = tid >> 6;   // pixel slice 0..3

    __shared__ int   s_x0[14], s_x1[14], s_y0[14], s_y1[14];
    __shared__ float s_dx0[14], s_dx1[14], s_dy0[14], s_dy1[14];

    // --- per-proposal setup (uniform across block) ---
    const float px1 = proposals[n * 4 + 0];
    const float py1 = proposals[n * 4 + 1];
    const float px2 = proposals[n * 4 + 2];
    const float py2 = proposals[n * 4 + 3];

    const float pw = px2 - px1;
    const float ph = py2 - py1;
    const float lf = floorf(2.0f + log2f(sqrtf(pw * ph) / 224.0f));
    int lvl = (int)lf;
    lvl = lvl < 0 ? 0 : (lvl > 3 ? 3 : lvl);

    const float scales[NLEV] = {0.25f, 0.125f, 0.0625f, 0.03125f};
    const int   sizes [NLEV] = {256, 128, 64, 32};
    const size_t offs [NLEV] = {0, 16777216, 16777216 + 4194304,
                                16777216 + 4194304 + 1048576};

    const float sc  = scales[lvl];
    const int   Sz  = sizes[lvl];
    const float bx1 = px1 * sc, by1 = py1 * sc;
    const float bx2 = px2 * sc, by2 = py2 * sc;
    const float w_unit = ((bx2 - bx1) / 7.0f) * 0.5f;
    const float h_unit = ((by2 - by1) / 7.0f) * 0.5f;

    if (tid < 14) {
        const float fi = (float)tid + 0.5f;
        {
            const float x  = bx1 + fi * w_unit;
            const int   xf = (int)floorf(x);
            int x0 = xf;     x0 = x0 < 0 ? 0 : (x0 > Sz - 1 ? Sz - 1 : x0);
            int x1 = xf + 1; x1 = x1 < 0 ? 0 : (x1 > Sz - 1 ? Sz - 1 : x1);
            s_x0[tid]  = x0;
            s_x1[tid]  = x1;
            s_dx0[tid] = x - (float)x0;   // (x - x0f)
            s_dx1[tid] = (float)x1 - x;   // (x1f - x)
        }
        {
            const float y  = by1 + fi * h_unit;
            const int   yf = (int)floorf(y);
            int y0 = yf;     y0 = y0 < 0 ? 0 : (y0 > Sz - 1 ? Sz - 1 : y0);
            int y1 = yf + 1; y1 = y1 < 0 ? 0 : (y1 > Sz - 1 ? Sz - 1 : y1);
            s_y0[tid]  = y0;
            s_y1[tid]  = y1;
            s_dy0[tid] = y - (float)y0;
            s_dy1[tid] = (float)y1 - y;
        }
    }
    __syncthreads();

    const float* __restrict__ fbase = g_featT + offs[lvl];
    const int cb = g * 4;

    for (int pix = p; pix < 49; pix += 4) {
        const int oy = pix / 7;
        const int ox = pix - oy * 7;

        float4 vmax = make_float4(-CUDART_INF_F, -CUDART_INF_F,
                                  -CUDART_INF_F, -CUDART_INF_F);
#pragma unroll
        for (int sy = 0; sy < 2; ++sy) {
            const int   gy  = oy * 2 + sy;
            const int   y0  = s_y0[gy], y1 = s_y1[gy];
            const float dy0 = s_dy0[gy], dy1 = s_dy1[gy];
#pragma unroll
            for (int sx = 0; sx < 2; ++sx) {
                const int   gx  = ox * 2 + sx;
                const int   x0  = s_x0[gx], x1 = s_x1[gx];
                const float dx0 = s_dx0[gx], dx1 = s_dx1[gx];

                const float wa = dx1 * dy1;
                const float wb = dx1 * dy0;
                const float wc = dx0 * dy1;
                const float wd = dx0 * dy0;

                const float4 la = *reinterpret_cast<const float4*>(
                    fbase + ((size_t)y0 * Sz + x0) * CCH + cb);
                const float4 lb = *reinterpret_cast<const float4*>(
                    fbase + ((size_t)y1 * Sz + x0) * CCH + cb);
                const float4 lc = *reinterpret_cast<const float4*>(
                    fbase + ((size_t)y0 * Sz + x1) * CCH + cb);
                const float4 ld = *reinterpret_cast<const float4*>(
                    fbase + ((size_t)y1 * Sz + x1) * CCH + cb);

                float4 v;
                v.x = wa * la.x + wb * lb.x + wc * lc.x + wd * ld.x;
                v.y = wa * la.y + wb * lb.y + wc * lc.y + wd * ld.y;
                v.z = wa * la.z + wb * lb.z + wc * lc.z + wd * ld.z;
                v.w = wa * la.w + wb * lb.w + wc * lc.w + wd * ld.w;

                vmax.x = fmaxf(vmax.x, v.x);
                vmax.y = fmaxf(vmax.y, v.y);
                vmax.z = fmaxf(vmax.z, v.z);
                vmax.w = fmaxf(vmax.w, v.w);
            }
        }

        // Stage in smem, layout = (C, 49) linear -> matches global layout.
        sOut[(cb + 0) * 49 + pix] = vmax.x;
        sOut[(cb + 1) * 49 + pix] = vmax.y;
        sOut[(cb + 2) * 49 + pix] = vmax.z;
        sOut[(cb + 3) * 49 + pix] = vmax.w;
    }

    __syncthreads();

    // Coalesced flush: straight float4 copy of the (C,7,7) tile.
    // n*12544 floats = n*50176 bytes -> 16B aligned. 12544/4 = 3136 float4.
    float4* __restrict__ o4 = reinterpret_cast<float4*>(out + (size_t)n * 12544);
    const float4* __restrict__ s4 = reinterpret_cast<const float4*>(sOut);
    for (int k = tid; k < 3136; k += 256) {
        o4[k] = s4[k];
    }
}

// ---------------------------------------------------------------------------
// Launch: 1 fused transpose + the ROIAlign kernel.
// Graph-capturable, allocation-free.
// ---------------------------------------------------------------------------
extern "C" void kernel_launch(void* const* d_in, const int* in_sizes, int n_in,
                              void* d_out, int out_size) {
    const float* p2 = (const float*)d_in[0];  // (1,256,256,256)
    const float* p3 = (const float*)d_in[1];  // (1,256,128,128)
    const float* p4 = (const float*)d_in[2];  // (1,256,64,64)
    const float* p5 = (const float*)d_in[3];  // (1,256,32,32)
    const float* proposals = (const float*)d_in[4];
    const int N = in_sizes[4] / 4;

    dim3 tb(32, 8);
    dim3 grid(2048, 8, 4);   // covers largest level; small levels early-exit
    transpose_all<<<grid, tb>>>(p2, p3, p4, p5);

    const int smemBytes = 256 * 49 * sizeof(float);   // 50176 B > 48KB default
    static bool attr_set = false;
    // Idempotent attribute set (not a stream op; safe under graph capture).
    cudaFuncSetAttribute(roialign_kernel,
                         cudaFuncAttributeMaxDynamicSharedMemorySize, smemBytes);
    (void)attr_set;

    roialign_kernel<<<N, 256, smemBytes>>>(proposals, (float*)d_out);
}

// round 3
// speedup vs baseline: 2.0292x; 2.0292x over previous
#include <cuda_runtime.h>
#include <math_constants.h>
#include <stdint.h>

#define CCH 256               // channels
#define NLEV 4

// Transposed scratch (HW, C) for all 4 pyramid levels, fp32.
// 65536*256 + 16384*256 + 4096*256 + 1024*256 = 22282240 floats (89.1 MB)
__device__ __align__(16) float g_featT[22282240];

// ---------------------------------------------------------------------------
// Transpose (C, HW) -> (HW, C) for one pyramid level. 32x33 smem tile,
// conflict-free, coalesced both directions. (Round-1 proven form.)
// ---------------------------------------------------------------------------
__global__ void transpose_chw_to_hwc(const float* __restrict__ in,
                                     size_t out_off, int HW) {
    __shared__ float tile[32][33];
    const int tx = threadIdx.x;          // 0..31
    const int ty = threadIdx.y;          // 0..7
    const int x  = blockIdx.x * 32 + tx; // HW index (read phase)
    const int c0 = blockIdx.y * 32;      // channel tile base

#pragma unroll
    for (int j = 0; j < 32; j += 8) {
        tile[ty + j][tx] = in[(size_t)(c0 + ty + j) * HW + x];
    }
    __syncthreads();

    const int xo = blockIdx.x * 32 + ty; // HW index (write phase)
#pragma unroll
    for (int j = 0; j < 32; j += 8) {
        g_featT[out_off + (size_t)(xo + j) * CCH + (c0 + tx)] = tile[tx][ty + j];
    }
}

// ---------------------------------------------------------------------------
// ROIAlign main kernel. Grid (N, 4): blockIdx.x = proposal, blockIdx.y =
// 64-channel chunk. 128 threads = 16 channel-groups (float4) x 8 pixel
// slices. Reads transposed features (HW, C); output staged in 12.25KB smem,
// then flushed as a linear float4 copy (fully coalesced stores).
// ---------------------------------------------------------------------------
__global__ __launch_bounds__(128) void roialign_kernel(
    const float* __restrict__ proposals,
    float* __restrict__ out) {

    __shared__ float sOut[64 * 49];   // 12544 B
    __shared__ int   s_x0[14], s_x1[14], s_y0[14], s_y1[14];
    __shared__ float s_dx0[14], s_dx1[14], s_dy0[14], s_dy1[14];

    const int n     = blockIdx.x;
    const int chunk = blockIdx.y;     // 0..3 -> channels chunk*64 .. +63
    const int tid   = threadIdx.x;
    const int g     = tid & 15;       // channel group within chunk
    const int p     = tid >> 4;       // pixel slice 0..7

    // --- per-proposal setup (uniform across block) ---
    const float px1 = proposals[n * 4 + 0];
    const float py1 = proposals[n * 4 + 1];
    const float px2 = proposals[n * 4 + 2];
    const float py2 = proposals[n * 4 + 3];

    const float pw = px2 - px1;
    const float ph = py2 - py1;
    const float lf = floorf(2.0f + log2f(sqrtf(pw * ph) / 224.0f));
    int lvl = (int)lf;
    lvl = lvl < 0 ? 0 : (lvl > 3 ? 3 : lvl);

    const float scales[NLEV] = {0.25f, 0.125f, 0.0625f, 0.03125f};
    const int   sizes [NLEV] = {256, 128, 64, 32};
    const size_t offs [NLEV] = {0, 16777216, 16777216 + 4194304,
                                16777216 + 4194304 + 1048576};

    const float sc  = scales[lvl];
    const int   Sz  = sizes[lvl];
    const float bx1 = px1 * sc, by1 = py1 * sc;
    const float bx2 = px2 * sc, by2 = py2 * sc;
    const float w_unit = ((bx2 - bx1) / 7.0f) * 0.5f;
    const float h_unit = ((by2 - by1) / 7.0f) * 0.5f;

    if (tid < 14) {
        const float fi = (float)tid + 0.5f;
        {
            const float x  = bx1 + fi * w_unit;
            const int   xf = (int)floorf(x);
            int x0 = xf;     x0 = x0 < 0 ? 0 : (x0 > Sz - 1 ? Sz - 1 : x0);
            int x1 = xf + 1; x1 = x1 < 0 ? 0 : (x1 > Sz - 1 ? Sz - 1 : x1);
            s_x0[tid]  = x0;
            s_x1[tid]  = x1;
            s_dx0[tid] = x - (float)x0;   // (x - x0f)
            s_dx1[tid] = (float)x1 - x;   // (x1f - x)
        }
        {
            const float y  = by1 + fi * h_unit;
            const int   yf = (int)floorf(y);
            int y0 = yf;     y0 = y0 < 0 ? 0 : (y0 > Sz - 1 ? Sz - 1 : y0);
            int y1 = yf + 1; y1 = y1 < 0 ? 0 : (y1 > Sz - 1 ? Sz - 1 : y1);
            s_y0[tid]  = y0;
            s_y1[tid]  = y1;
            s_dy0[tid] = y - (float)y0;
            s_dy1[tid] = (float)y1 - y;
        }
    }
    __syncthreads();

    const float* __restrict__ fbase = g_featT + offs[lvl];
    const int cb = g * 4;                    // channel within chunk (0..60)
    const int cg = chunk * 64 + cb;          // global channel

    for (int pix = p; pix < 49; pix += 8) {
        const int oy = pix / 7;
        const int ox = pix - oy * 7;

        float4 vmax = make_float4(-CUDART_INF_F, -CUDART_INF_F,
                                  -CUDART_INF_F, -CUDART_INF_F);
#pragma unroll
        for (int sy = 0; sy < 2; ++sy) {
            const int   gy  = oy * 2 + sy;
            const int   y0  = s_y0[gy], y1 = s_y1[gy];
            const float dy0 = s_dy0[gy], dy1 = s_dy1[gy];
#pragma unroll
            for (int sx = 0; sx < 2; ++sx) {
                const int   gx  = ox * 2 + sx;
                const int   x0  = s_x0[gx], x1 = s_x1[gx];
                const float dx0 = s_dx0[gx], dx1 = s_dx1[gx];

                const float wa = dx1 * dy1;
                const float wb = dx1 * dy0;
                const float wc = dx0 * dy1;
                const float wd = dx0 * dy0;

                const float4 la = *reinterpret_cast<const float4*>(
                    fbase + ((size_t)y0 * Sz + x0) * CCH + cg);
                const float4 lb = *reinterpret_cast<const float4*>(
                    fbase + ((size_t)y1 * Sz + x0) * CCH + cg);
                const float4 lc = *reinterpret_cast<const float4*>(
                    fbase + ((size_t)y0 * Sz + x1) * CCH + cg);
                const float4 ld = *reinterpret_cast<const float4*>(
                    fbase + ((size_t)y1 * Sz + x1) * CCH + cg);

                float4 v;
                v.x = wa * la.x + wb * lb.x + wc * lc.x + wd * ld.x;
                v.y = wa * la.y + wb * lb.y + wc * lc.y + wd * ld.y;
                v.z = wa * la.z + wb * lb.z + wc * lc.z + wd * ld.z;
                v.w = wa * la.w + wb * lb.w + wc * lc.w + wd * ld.w;

                vmax.x = fmaxf(vmax.x, v.x);
                vmax.y = fmaxf(vmax.y, v.y);
                vmax.z = fmaxf(vmax.z, v.z);
                vmax.w = fmaxf(vmax.w, v.w);
            }
        }

        // Stage in smem: layout (64, 49) matches global (C,7,7) slice.
        sOut[(cb + 0) * 49 + pix] = vmax.x;
        sOut[(cb + 1) * 49 + pix] = vmax.y;
        sOut[(cb + 2) * 49 + pix] = vmax.z;
        sOut[(cb + 3) * 49 + pix] = vmax.w;
    }

    __syncthreads();

    // Coalesced flush: 64*49 = 3136 floats = 784 float4.
    // Offset n*12544 + chunk*3136 floats; both multiples of 4 -> 16B aligned.
    float4* __restrict__ o4 = reinterpret_cast<float4*>(
        out + (size_t)n * 12544 + (size_t)chunk * 3136);
    const float4* __restrict__ s4 = reinterpret_cast<const float4*>(sOut);
    for (int k = tid; k < 784; k += 128) {
        o4[k] = s4[k];
    }
}

// ---------------------------------------------------------------------------
// Launch: 4 transposes (round-1 form) + the ROIAlign kernel.
// Graph-capturable, allocation-free.
// ---------------------------------------------------------------------------
extern "C" void kernel_launch(void* const* d_in, const int* in_sizes, int n_in,
                              void* d_out, int out_size) {
    const float* feats[NLEV] = {
        (const float*)d_in[0],  // p2: (1,256,256,256)
        (const float*)d_in[1],  // p3: (1,256,128,128)
        (const float*)d_in[2],  // p4: (1,256,64,64)
        (const float*)d_in[3],  // p5: (1,256,32,32)
    };
    const float* proposals = (const float*)d_in[4];
    const int N = in_sizes[4] / 4;

    const int    HWs [NLEV] = {65536, 16384, 4096, 1024};
    const size_t offs[NLEV] = {0, 16777216, 16777216 + 4194304,
                               16777216 + 4194304 + 1048576};

    dim3 tb(32, 8);
    for (int l = 0; l < NLEV; ++l) {
        dim3 grid(HWs[l] / 32, CCH / 32);
        transpose_chw_to_hwc<<<grid, tb>>>(feats[l], offs[l], HWs[l]);
    }

    dim3 rg(N, 4);
    roialign_kernel<<<rg, 128>>>(proposals, (float*)d_out);
}

// round 4
// speedup vs baseline: 2.5365x; 1.2500x over previous
#include <cuda_runtime.h>
#include <cuda_fp16.h>
#include <math_constants.h>
#include <stdint.h>

#define CCH 256               // channels
#define NLEV 4

// Transposed scratch (HW, C) for all 4 pyramid levels, fp16.
// 65536*256 + 16384*256 + 4096*256 + 1024*256 = 22282240 halves (44.6 MB)
__device__ __align__(16) __half g_featT[22282240];

// ---------------------------------------------------------------------------
// Transpose (C, HW) -> (HW, C) fp32 -> fp16. 32x33 smem tile, conflict-free,
// coalesced both directions.
// ---------------------------------------------------------------------------
__global__ void transpose_chw_to_hwc(const float* __restrict__ in,
                                     size_t out_off, int HW) {
    __shared__ float tile[32][33];
    const int tx = threadIdx.x;          // 0..31
    const int ty = threadIdx.y;          // 0..7
    const int x  = blockIdx.x * 32 + tx; // HW index (read phase)
    const int c0 = blockIdx.y * 32;      // channel tile base

#pragma unroll
    for (int j = 0; j < 32; j += 8) {
        tile[ty + j][tx] = in[(size_t)(c0 + ty + j) * HW + x];
    }
    __syncthreads();

    const int xo = blockIdx.x * 32 + ty; // HW index (write phase)
#pragma unroll
    for (int j = 0; j < 32; j += 8) {
        g_featT[out_off + (size_t)(xo + j) * CCH + (c0 + tx)] =
            __float2half(tile[tx][ty + j]);
    }
}

// ---------------------------------------------------------------------------
// ROIAlign main kernel. Grid (N, 4): blockIdx.x = proposal, blockIdx.y =
// 64-channel chunk. 128 threads = 8 channel-groups (8 ch = one uint4 of
// halves) x 16 pixel slices. Bilinear math in fp32; features fp16.
// Output staged in smem, flushed as linear float4 copy (coalesced).
// ---------------------------------------------------------------------------
__global__ __launch_bounds__(128) void roialign_kernel(
    const float* __restrict__ proposals,
    float* __restrict__ out) {

    __shared__ float sOut[64 * 49];   // 12544 B
    __shared__ int   s_x0[14], s_x1[14], s_y0[14], s_y1[14];
    __shared__ float s_dx0[14], s_dx1[14], s_dy0[14], s_dy1[14];

    const int n     = blockIdx.x;
    const int chunk = blockIdx.y;     // 0..3 -> channels chunk*64 .. +63
    const int tid   = threadIdx.x;
    const int g     = tid & 7;        // channel group (8 channels each)
    const int p     = tid >> 3;       // pixel slice 0..15

    // --- per-proposal setup (uniform across block) ---
    const float px1 = proposals[n * 4 + 0];
    const float py1 = proposals[n * 4 + 1];
    const float px2 = proposals[n * 4 + 2];
    const float py2 = proposals[n * 4 + 3];

    const float pw = px2 - px1;
    const float ph = py2 - py1;
    const float lf = floorf(2.0f + log2f(sqrtf(pw * ph) / 224.0f));
    int lvl = (int)lf;
    lvl = lvl < 0 ? 0 : (lvl > 3 ? 3 : lvl);

    const float scales[NLEV] = {0.25f, 0.125f, 0.0625f, 0.03125f};
    const int   sizes [NLEV] = {256, 128, 64, 32};
    const size_t offs [NLEV] = {0, 16777216, 16777216 + 4194304,
                                16777216 + 4194304 + 1048576};

    const float sc  = scales[lvl];
    const int   Sz  = sizes[lvl];
    const float bx1 = px1 * sc, by1 = py1 * sc;
    const float bx2 = px2 * sc, by2 = py2 * sc;
    const float w_unit = ((bx2 - bx1) / 7.0f) * 0.5f;
    const float h_unit = ((by2 - by1) / 7.0f) * 0.5f;

    if (tid < 14) {
        const float fi = (float)tid + 0.5f;
        {
            const float x  = bx1 + fi * w_unit;
            const int   xf = (int)floorf(x);
            int x0 = xf;     x0 = x0 < 0 ? 0 : (x0 > Sz - 1 ? Sz - 1 : x0);
            int x1 = xf + 1; x1 = x1 < 0 ? 0 : (x1 > Sz - 1 ? Sz - 1 : x1);
            s_x0[tid]  = x0;
            s_x1[tid]  = x1;
            s_dx0[tid] = x - (float)x0;   // (x - x0f)
            s_dx1[tid] = (float)x1 - x;   // (x1f - x)
        }
        {
            const float y  = by1 + fi * h_unit;
            const int   yf = (int)floorf(y);
            int y0 = yf;     y0 = y0 < 0 ? 0 : (y0 > Sz - 1 ? Sz - 1 : y0);
            int y1 = yf + 1; y1 = y1 < 0 ? 0 : (y1 > Sz - 1 ? Sz - 1 : y1);
            s_y0[tid]  = y0;
            s_y1[tid]  = y1;
            s_dy0[tid] = y - (float)y0;
            s_dy1[tid] = (float)y1 - y;
        }
    }
    __syncthreads();

    const __half* __restrict__ fbase = g_featT + offs[lvl];
    const int cb = g * 8;                    // channel within chunk (0..56)
    const int cg = chunk * 64 + cb;          // global channel

    for (int pix = p; pix < 49; pix += 16) {
        const int oy = pix / 7;
        const int ox = pix - oy * 7;

        float vmax[8];
#pragma unroll
        for (int c = 0; c < 8; ++c) vmax[c] = -CUDART_INF_F;

#pragma unroll
        for (int sy = 0; sy < 2; ++sy) {
            const int   gy  = oy * 2 + sy;
            const int   y0  = s_y0[gy], y1 = s_y1[gy];
            const float dy0 = s_dy0[gy], dy1 = s_dy1[gy];
#pragma unroll
            for (int sx = 0; sx < 2; ++sx) {
                const int   gx  = ox * 2 + sx;
                const int   x0  = s_x0[gx], x1 = s_x1[gx];
                const float dx0 = s_dx0[gx], dx1 = s_dx1[gx];

                const float wa = dx1 * dy1;
                const float wb = dx1 * dy0;
                const float wc = dx0 * dy1;
                const float wd = dx0 * dy0;

                // 8 halves (16B) per corner, contiguous per warp.
                const uint4 ua = *reinterpret_cast<const uint4*>(
                    fbase + ((size_t)y0 * Sz + x0) * CCH + cg);
                const uint4 ub = *reinterpret_cast<const uint4*>(
                    fbase + ((size_t)y1 * Sz + x0) * CCH + cg);
                const uint4 uc = *reinterpret_cast<const uint4*>(
                    fbase + ((size_t)y0 * Sz + x1) * CCH + cg);
                const uint4 ud = *reinterpret_cast<const uint4*>(
                    fbase + ((size_t)y1 * Sz + x1) * CCH + cg);

                const __half2* ha = reinterpret_cast<const __half2*>(&ua);
                const __half2* hb = reinterpret_cast<const __half2*>(&ub);
                const __half2* hc = reinterpret_cast<const __half2*>(&uc);
                const __half2* hd = reinterpret_cast<const __half2*>(&ud);

#pragma unroll
                for (int q = 0; q < 4; ++q) {
                    const float2 fa = __half22float2(ha[q]);
                    const float2 fb = __half22float2(hb[q]);
                    const float2 fc = __half22float2(hc[q]);
                    const float2 fd = __half22float2(hd[q]);

                    float v0 = wa * fa.x + wb * fb.x + wc * fc.x + wd * fd.x;
                    float v1 = wa * fa.y + wb * fb.y + wc * fc.y + wd * fd.y;
                    vmax[q * 2 + 0] = fmaxf(vmax[q * 2 + 0], v0);
                    vmax[q * 2 + 1] = fmaxf(vmax[q * 2 + 1], v1);
                }
            }
        }

        // Stage in smem: layout (64, 49) matches global (C,7,7) slice.
#pragma unroll
        for (int c = 0; c < 8; ++c) {
            sOut[(cb + c) * 49 + pix] = vmax[c];
        }
    }

    __syncthreads();

    // Coalesced flush: 64*49 = 3136 floats = 784 float4.
    float4* __restrict__ o4 = reinterpret_cast<float4*>(
        out + (size_t)n * 12544 + (size_t)chunk * 3136);
    const float4* __restrict__ s4 = reinterpret_cast<const float4*>(sOut);
    for (int k = tid; k < 784; k += 128) {
        o4[k] = s4[k];
    }
}

// ---------------------------------------------------------------------------
// Launch: 4 transposes + the ROIAlign kernel. Graph-capturable, alloc-free.
// ---------------------------------------------------------------------------
extern "C" void kernel_launch(void* const* d_in, const int* in_sizes, int n_in,
                              void* d_out, int out_size) {
    const float* feats[NLEV] = {
        (const float*)d_in[0],  // p2: (1,256,256,256)
        (const float*)d_in[1],  // p3: (1,256,128,128)
        (const float*)d_in[2],  // p4: (1,256,64,64)
        (const float*)d_in[3],  // p5: (1,256,32,32)
    };
    const float* proposals = (const float*)d_in[4];
    const int N = in_sizes[4] / 4;

    const int    HWs [NLEV] = {65536, 16384, 4096, 1024};
    const size_t offs[NLEV] = {0, 16777216, 16777216 + 4194304,
                               16777216 + 4194304 + 1048576};

    dim3 tb(32, 8);
    for (int l = 0; l < NLEV; ++l) {
        dim3 grid(HWs[l] / 32, CCH / 32);
        transpose_chw_to_hwc<<<grid, tb>>>(feats[l], offs[l], HWs[l]);
    }

    dim3 rg(N, 4);
    roialign_kernel<<<rg, 128>>>(proposals, (float*)d_out);
}

// round 5
// speedup vs baseline: 2.6511x; 1.0452x over previous
#include <cuda_runtime.h>
#include <cuda_fp16.h>
#include <math_constants.h>
#include <stdint.h>

#define CCH 256               // channels
#define NLEV 4

// Transposed scratch (HW, C) for all 4 pyramid levels, fp16.
// 65536*256 + 16384*256 + 4096*256 + 1024*256 = 22282240 halves (44.6 MB)
__device__ __align__(16) __half g_featT[22282240];

// ---------------------------------------------------------------------------
// Transpose (C, HW) -> (HW, C) fp32 -> fp16. 32x33 smem tile, conflict-free,
// coalesced both directions.
// ---------------------------------------------------------------------------
__global__ void transpose_chw_to_hwc(const float* __restrict__ in,
                                     size_t out_off, int HW) {
    __shared__ float tile[32][33];
    const int tx = threadIdx.x;          // 0..31
    const int ty = threadIdx.y;          // 0..7
    const int x  = blockIdx.x * 32 + tx; // HW index (read phase)
    const int c0 = blockIdx.y * 32;      // channel tile base

#pragma unroll
    for (int j = 0; j < 32; j += 8) {
        tile[ty + j][tx] = in[(size_t)(c0 + ty + j) * HW + x];
    }
    __syncthreads();

    const int xo = blockIdx.x * 32 + ty; // HW index (write phase)
#pragma unroll
    for (int j = 0; j < 32; j += 8) {
        g_featT[out_off + (size_t)(xo + j) * CCH + (c0 + tx)] =
            __float2half(tile[tx][ty + j]);
    }
}

// ---------------------------------------------------------------------------
// ROIAlign main kernel. Grid (N, 4): blockIdx.x = proposal, blockIdx.y =
// 64-channel chunk. 128 threads = 8 channel-groups (8 ch = one uint4 of
// halves) x 16 pixel slices. Bilinear math in fp32; features fp16.
// Output staged in smem, flushed as linear float4 copy (coalesced).
// ---------------------------------------------------------------------------
__global__ __launch_bounds__(128) void roialign_kernel(
    const float* __restrict__ proposals,
    float* __restrict__ out) {

    __shared__ float sOut[64 * 49];   // 12544 B
    __shared__ int   s_x0[14], s_x1[14], s_y0[14], s_y1[14];
    __shared__ float s_dx0[14], s_dx1[14], s_dy0[14], s_dy1[14];

    const int n     = blockIdx.x;
    const int chunk = blockIdx.y;     // 0..3 -> channels chunk*64 .. +63
    const int tid   = threadIdx.x;
    const int g     = tid & 7;        // channel group (8 channels each)
    const int p     = tid >> 3;       // pixel slice 0..15

    // --- per-proposal setup (uniform across block) ---
    const float px1 = proposals[n * 4 + 0];
    const float py1 = proposals[n * 4 + 1];
    const float px2 = proposals[n * 4 + 2];
    const float py2 = proposals[n * 4 + 3];

    const float pw = px2 - px1;
    const float ph = py2 - py1;
    const float lf = floorf(2.0f + log2f(sqrtf(pw * ph) / 224.0f));
    int lvl = (int)lf;
    lvl = lvl < 0 ? 0 : (lvl > 3 ? 3 : lvl);

    const float scales[NLEV] = {0.25f, 0.125f, 0.0625f, 0.03125f};
    const int   sizes [NLEV] = {256, 128, 64, 32};
    const size_t offs [NLEV] = {0, 16777216, 16777216 + 4194304,
                                16777216 + 4194304 + 1048576};

    const float sc  = scales[lvl];
    const int   Sz  = sizes[lvl];
    const float bx1 = px1 * sc, by1 = py1 * sc;
    const float bx2 = px2 * sc, by2 = py2 * sc;
    const float w_unit = ((bx2 - bx1) / 7.0f) * 0.5f;
    const float h_unit = ((by2 - by1) / 7.0f) * 0.5f;

    if (tid < 14) {
        const float fi = (float)tid + 0.5f;
        {
            const float x  = bx1 + fi * w_unit;
            const int   xf = (int)floorf(x);
            int x0 = xf;     x0 = x0 < 0 ? 0 : (x0 > Sz - 1 ? Sz - 1 : x0);
            int x1 = xf + 1; x1 = x1 < 0 ? 0 : (x1 > Sz - 1 ? Sz - 1 : x1);
            s_x0[tid]  = x0;
            s_x1[tid]  = x1;
            s_dx0[tid] = x - (float)x0;   // (x - x0f)
            s_dx1[tid] = (float)x1 - x;   // (x1f - x)
        }
        {
            const float y  = by1 + fi * h_unit;
            const int   yf = (int)floorf(y);
            int y0 = yf;     y0 = y0 < 0 ? 0 : (y0 > Sz - 1 ? Sz - 1 : y0);
            int y1 = yf + 1; y1 = y1 < 0 ? 0 : (y1 > Sz - 1 ? Sz - 1 : y1);
            s_y0[tid]  = y0;
            s_y1[tid]  = y1;
            s_dy0[tid] = y - (float)y0;
            s_dy1[tid] = (float)y1 - y;
        }
    }
    __syncthreads();

    const __half* __restrict__ fbase = g_featT + offs[lvl];
    const int cb = g * 8;                    // channel within chunk (0..56)
    const int cg = chunk * 64 + cb;          // global channel

    for (int pix = p; pix < 49; pix += 16) {
        const int oy = pix / 7;
        const int ox = pix - oy * 7;

        float vmax[8];
#pragma unroll
        for (int c = 0; c < 8; ++c) vmax[c] = -CUDART_INF_F;

#pragma unroll
        for (int sy = 0; sy < 2; ++sy) {
            const int   gy  = oy * 2 + sy;
            const int   y0  = s_y0[gy], y1 = s_y1[gy];
            const float dy0 = s_dy0[gy], dy1 = s_dy1[gy];
#pragma unroll
            for (int sx = 0; sx < 2; ++sx) {
                const int   gx  = ox * 2 + sx;
                const int   x0  = s_x0[gx], x1 = s_x1[gx];
                const float dx0 = s_dx0[gx], dx1 = s_dx1[gx];

                const float wa = dx1 * dy1;
                const float wb = dx1 * dy0;
                const float wc = dx0 * dy1;
                const float wd = dx0 * dy0;

                // 8 halves (16B) per corner, contiguous per warp.
                const uint4 ua = *reinterpret_cast<const uint4*>(
                    fbase + ((size_t)y0 * Sz + x0) * CCH + cg);
                const uint4 ub = *reinterpret_cast<const uint4*>(
                    fbase + ((size_t)y1 * Sz + x0) * CCH + cg);
                const uint4 uc = *reinterpret_cast<const uint4*>(
                    fbase + ((size_t)y0 * Sz + x1) * CCH + cg);
                const uint4 ud = *reinterpret_cast<const uint4*>(
                    fbase + ((size_t)y1 * Sz + x1) * CCH + cg);

                const __half2* ha = reinterpret_cast<const __half2*>(&ua);
                const __half2* hb = reinterpret_cast<const __half2*>(&ub);
                const __half2* hc = reinterpret_cast<const __half2*>(&uc);
                const __half2* hd = reinterpret_cast<const __half2*>(&ud);

#pragma unroll
                for (int q = 0; q < 4; ++q) {
                    const float2 fa = __half22float2(ha[q]);
                    const float2 fb = __half22float2(hb[q]);
                    const float2 fc = __half22float2(hc[q]);
                    const float2 fd = __half22float2(hd[q]);

                    float v0 = wa * fa.x + wb * fb.x + wc * fc.x + wd * fd.x;
                    float v1 = wa * fa.y + wb * fb.y + wc * fc.y + wd * fd.y;
                    vmax[q * 2 + 0] = fmaxf(vmax[q * 2 + 0], v0);
                    vmax[q * 2 + 1] = fmaxf(vmax[q * 2 + 1], v1);
                }
            }
        }

        // Stage in smem: layout (64, 49) matches global (C,7,7) slice.
#pragma unroll
        for (int c = 0; c < 8; ++c) {
            sOut[(cb + c) * 49 + pix] = vmax[c];
        }
    }

    __syncthreads();

    // Coalesced flush: 64*49 = 3136 floats = 784 float4.
    float4* __restrict__ o4 = reinterpret_cast<float4*>(
        out + (size_t)n * 12544 + (size_t)chunk * 3136);
    const float4* __restrict__ s4 = reinterpret_cast<const float4*>(sOut);
    for (int k = tid; k < 784; k += 128) {
        o4[k] = s4[k];
    }
}

// ---------------------------------------------------------------------------
// Launch: p2 transpose on main stream; p3/p4/p5 on side streams (forked via
// events so graph capture records them as parallel branches); join, then ROI.
// Streams/events are created once on the first (uncaptured) correctness call.
// No device-memory allocation anywhere.
// ---------------------------------------------------------------------------
extern "C" void kernel_launch(void* const* d_in, const int* in_sizes, int n_in,
                              void* d_out, int out_size) {
    const float* p2 = (const float*)d_in[0];  // (1,256,256,256)
    const float* p3 = (const float*)d_in[1];  // (1,256,128,128)
    const float* p4 = (const float*)d_in[2];  // (1,256,64,64)
    const float* p5 = (const float*)d_in[3];  // (1,256,32,32)
    const float* proposals = (const float*)d_in[4];
    const int N = in_sizes[4] / 4;

    const int    HWs [NLEV] = {65536, 16384, 4096, 1024};
    const size_t offs[NLEV] = {0, 16777216, 16777216 + 4194304,
                               16777216 + 4194304 + 1048576};

    static cudaStream_t s1 = nullptr, s2 = nullptr;
    static cudaEvent_t evRoot = nullptr, ev1 = nullptr, ev2 = nullptr;
    if (s1 == nullptr) {
        cudaStreamCreateWithFlags(&s1, cudaStreamNonBlocking);
        cudaStreamCreateWithFlags(&s2, cudaStreamNonBlocking);
        cudaEventCreateWithFlags(&evRoot, cudaEventDisableTiming);
        cudaEventCreateWithFlags(&ev1, cudaEventDisableTiming);
        cudaEventCreateWithFlags(&ev2, cudaEventDisableTiming);
    }

    dim3 tb(32, 8);

    // Fork side streams off the main (capture) stream.
    cudaEventRecord(evRoot, 0);
    cudaStreamWaitEvent(s1, evRoot, 0);
    cudaStreamWaitEvent(s2, evRoot, 0);

    // Big level on the main stream.
    {
        dim3 grid(HWs[0] / 32, CCH / 32);
        transpose_chw_to_hwc<<<grid, tb>>>(p2, offs[0], HWs[0]);
    }
    // Small levels hidden on side streams.
    {
        dim3 g3(HWs[1] / 32, CCH / 32);
        transpose_chw_to_hwc<<<g3, tb, 0, s1>>>(p3, offs[1], HWs[1]);
        dim3 g5(HWs[3] / 32, CCH / 32);
        transpose_chw_to_hwc<<<g5, tb, 0, s1>>>(p5, offs[3], HWs[3]);
        dim3 g4(HWs[2] / 32, CCH / 32);
        transpose_chw_to_hwc<<<g4, tb, 0, s2>>>(p4, offs[2], HWs[2]);
    }

    // Join side streams back into the main stream.
    cudaEventRecord(ev1, s1);
    cudaEventRecord(ev2, s2);
    cudaStreamWaitEvent(0, ev1, 0);
    cudaStreamWaitEvent(0, ev2, 0);

    dim3 rg(N, 4);
    roialign_kernel<<<rg, 128>>>(proposals, (float*)d_out);
}

// round 6
// speedup vs baseline: 2.9976x; 1.1307x over previous
#include <cuda_runtime.h>
#include <cuda_fp16.h>
#include <math_constants.h>
#include <stdint.h>

#define CCH 256               // channels
#define NLEV 4

// Transposed scratch (HW, C) for all 4 pyramid levels, fp16.
// 65536*256 + 16384*256 + 4096*256 + 1024*256 = 22282240 halves (44.6 MB)
__device__ __align__(16) __half g_featT[22282240];

// ---------------------------------------------------------------------------
// Transpose (C, HW) -> (HW, C), fp32 -> fp16. Per block: 64 channels x 32 HW.
// Channels are packed in pairs to __half2 at read time; smem tile is
// 32x33 half2 (conflict-free both phases); write phase stores 128B
// contiguous per warp (STG.32 of half2).
// ---------------------------------------------------------------------------
__global__ void transpose_chw_to_hwc(const float* __restrict__ in,
                                     size_t out_off, int HW) {
    __shared__ __half2 tile[32][33];   // [hw][channel-pair]
    const int tx = threadIdx.x;          // 0..31 -> hw within tile
    const int ty = threadIdx.y;          // 0..7
    const int x  = blockIdx.x * 32 + tx; // HW index
    const int c0 = blockIdx.y * 64;      // channel tile base (64 channels)

#pragma unroll
    for (int j = 0; j < 32; j += 8) {
        const int k = ty + j;            // channel-pair index 0..31
        const float f0 = in[(size_t)(c0 + 2 * k + 0) * HW + x];
        const float f1 = in[(size_t)(c0 + 2 * k + 1) * HW + x];
        tile[tx][k] = __floats2half2_rn(f0, f1);
    }
    __syncthreads();

    const int xo = blockIdx.x * 32;
#pragma unroll
    for (int r0 = 0; r0 < 32; r0 += 8) {
        const int r = r0 + ty;           // hw row within tile
        // warp writes 32 half2 = 128B contiguous
        *reinterpret_cast<__half2*>(
            &g_featT[out_off + (size_t)(xo + r) * CCH + c0 + 2 * tx]) =
            tile[r][tx];
    }
}

// ---------------------------------------------------------------------------
// ROIAlign kernel, per-level gated. Grid (N, 4): blockIdx.x = proposal,
// blockIdx.y = 64-channel chunk. Blocks whose proposal level doesn't match
// target_lvl exit early (uniform per block, before any __syncthreads).
// target_lvl: 0 -> lvl==0, 1 -> lvl==1, 2 -> lvl>=2.
// ---------------------------------------------------------------------------
__global__ __launch_bounds__(128) void roialign_kernel(
    const float* __restrict__ proposals,
    float* __restrict__ out,
    int target_lvl) {

    __shared__ float sOut[64 * 49];   // 12544 B
    __shared__ int   s_x0[14], s_x1[14], s_y0[14], s_y1[14];
    __shared__ float s_dx0[14], s_dx1[14], s_dy0[14], s_dy1[14];

    const int n     = blockIdx.x;
    const int chunk = blockIdx.y;     // 0..3 -> channels chunk*64 .. +63
    const int tid   = threadIdx.x;
    const int g     = tid & 7;        // channel group (8 channels each)
    const int p     = tid >> 3;       // pixel slice 0..15

    // --- per-proposal setup (uniform across block) ---
    const float px1 = proposals[n * 4 + 0];
    const float py1 = proposals[n * 4 + 1];
    const float px2 = proposals[n * 4 + 2];
    const float py2 = proposals[n * 4 + 3];

    const float pw = px2 - px1;
    const float ph = py2 - py1;
    const float lf = floorf(2.0f + log2f(sqrtf(pw * ph) / 224.0f));
    int lvl = (int)lf;
    lvl = lvl < 0 ? 0 : (lvl > 3 ? 3 : lvl);

    // Level gate: this launch handles only its level class (uniform branch,
    // taken before any __syncthreads -> safe).
    const int lvlClass = lvl >= 2 ? 2 : lvl;
    if (lvlClass != target_lvl) return;

    const float scales[NLEV] = {0.25f, 0.125f, 0.0625f, 0.03125f};
    const int   sizes [NLEV] = {256, 128, 64, 32};
    const size_t offs [NLEV] = {0, 16777216, 16777216 + 4194304,
                                16777216 + 4194304 + 1048576};

    const float sc  = scales[lvl];
    const int   Sz  = sizes[lvl];
    const float bx1 = px1 * sc, by1 = py1 * sc;
    const float bx2 = px2 * sc, by2 = py2 * sc;
    const float w_unit = ((bx2 - bx1) / 7.0f) * 0.5f;
    const float h_unit = ((by2 - by1) / 7.0f) * 0.5f;

    if (tid < 14) {
        const float fi = (float)tid + 0.5f;
        {
            const float x  = bx1 + fi * w_unit;
            const int   xf = (int)floorf(x);
            int x0 = xf;     x0 = x0 < 0 ? 0 : (x0 > Sz - 1 ? Sz - 1 : x0);
            int x1 = xf + 1; x1 = x1 < 0 ? 0 : (x1 > Sz - 1 ? Sz - 1 : x1);
            s_x0[tid]  = x0;
            s_x1[tid]  = x1;
            s_dx0[tid] = x - (float)x0;   // (x - x0f)
            s_dx1[tid] = (float)x1 - x;   // (x1f - x)
        }
        {
            const float y  = by1 + fi * h_unit;
            const int   yf = (int)floorf(y);
            int y0 = yf;     y0 = y0 < 0 ? 0 : (y0 > Sz - 1 ? Sz - 1 : y0);
            int y1 = yf + 1; y1 = y1 < 0 ? 0 : (y1 > Sz - 1 ? Sz - 1 : y1);
            s_y0[tid]  = y0;
            s_y1[tid]  = y1;
            s_dy0[tid] = y - (float)y0;
            s_dy1[tid] = (float)y1 - y;
        }
    }
    __syncthreads();

    const __half* __restrict__ fbase = g_featT + offs[lvl];
    const int cb = g * 8;                    // channel within chunk (0..56)
    const int cg = chunk * 64 + cb;          // global channel

    for (int pix = p; pix < 49; pix += 16) {
        const int oy = pix / 7;
        const int ox = pix - oy * 7;

        float vmax[8];
#pragma unroll
        for (int c = 0; c < 8; ++c) vmax[c] = -CUDART_INF_F;

#pragma unroll
        for (int sy = 0; sy < 2; ++sy) {
            const int   gy  = oy * 2 + sy;
            const int   y0  = s_y0[gy], y1 = s_y1[gy];
            const float dy0 = s_dy0[gy], dy1 = s_dy1[gy];
#pragma unroll
            for (int sx = 0; sx < 2; ++sx) {
                const int   gx  = ox * 2 + sx;
                const int   x0  = s_x0[gx], x1 = s_x1[gx];
                const float dx0 = s_dx0[gx], dx1 = s_dx1[gx];

                const float wa = dx1 * dy1;
                const float wb = dx1 * dy0;
                const float wc = dx0 * dy1;
                const float wd = dx0 * dy0;

                // 8 halves (16B) per corner, contiguous per warp.
                const uint4 ua = *reinterpret_cast<const uint4*>(
                    fbase + ((size_t)y0 * Sz + x0) * CCH + cg);
                const uint4 ub = *reinterpret_cast<const uint4*>(
                    fbase + ((size_t)y1 * Sz + x0) * CCH + cg);
                const uint4 uc = *reinterpret_cast<const uint4*>(
                    fbase + ((size_t)y0 * Sz + x1) * CCH + cg);
                const uint4 ud = *reinterpret_cast<const uint4*>(
                    fbase + ((size_t)y1 * Sz + x1) * CCH + cg);

                const __half2* ha = reinterpret_cast<const __half2*>(&ua);
                const __half2* hb = reinterpret_cast<const __half2*>(&ub);
                const __half2* hc = reinterpret_cast<const __half2*>(&uc);
                const __half2* hd = reinterpret_cast<const __half2*>(&ud);

#pragma unroll
                for (int q = 0; q < 4; ++q) {
                    const float2 fa = __half22float2(ha[q]);
                    const float2 fb = __half22float2(hb[q]);
                    const float2 fc = __half22float2(hc[q]);
                    const float2 fd = __half22float2(hd[q]);

                    float v0 = wa * fa.x + wb * fb.x + wc * fc.x + wd * fd.x;
                    float v1 = wa * fa.y + wb * fb.y + wc * fc.y + wd * fd.y;
                    vmax[q * 2 + 0] = fmaxf(vmax[q * 2 + 0], v0);
                    vmax[q * 2 + 1] = fmaxf(vmax[q * 2 + 1], v1);
                }
            }
        }

#pragma unroll
        for (int c = 0; c < 8; ++c) {
            sOut[(cb + c) * 49 + pix] = vmax[c];
        }
    }

    __syncthreads();

    // Coalesced flush: 64*49 = 3136 floats = 784 float4.
    float4* __restrict__ o4 = reinterpret_cast<float4*>(
        out + (size_t)n * 12544 + (size_t)chunk * 3136);
    const float4* __restrict__ s4 = reinterpret_cast<const float4*>(sOut);
    for (int k = tid; k < 784; k += 128) {
        o4[k] = s4[k];
    }
}

// ---------------------------------------------------------------------------
// Launch graph:
//   main: T(p2) -> ROI(lvl0)
//   s1:   T(p3) -> ROI(lvl1)
//   s2:   T(p4) -> T(p5) -> ROI(lvl>=2)
// ROI work for levels 1/2 overlaps the big p2 transpose instead of waiting
// for it. Streams/events created once on the first (uncaptured) call.
// ---------------------------------------------------------------------------
extern "C" void kernel_launch(void* const* d_in, const int* in_sizes, int n_in,
                              void* d_out, int out_size) {
    const float* p2 = (const float*)d_in[0];  // (1,256,256,256)
    const float* p3 = (const float*)d_in[1];  // (1,256,128,128)
    const float* p4 = (const float*)d_in[2];  // (1,256,64,64)
    const float* p5 = (const float*)d_in[3];  // (1,256,32,32)
    const float* proposals = (const float*)d_in[4];
    const int N = in_sizes[4] / 4;

    const int    HWs [NLEV] = {65536, 16384, 4096, 1024};
    const size_t offs[NLEV] = {0, 16777216, 16777216 + 4194304,
                               16777216 + 4194304 + 1048576};

    static cudaStream_t s1 = nullptr, s2 = nullptr;
    static cudaEvent_t evRoot = nullptr, ev1 = nullptr, ev2 = nullptr;
    if (s1 == nullptr) {
        cudaStreamCreateWithFlags(&s1, cudaStreamNonBlocking);
        cudaStreamCreateWithFlags(&s2, cudaStreamNonBlocking);
        cudaEventCreateWithFlags(&evRoot, cudaEventDisableTiming);
        cudaEventCreateWithFlags(&ev1, cudaEventDisableTiming);
        cudaEventCreateWithFlags(&ev2, cudaEventDisableTiming);
    }

    dim3 tb(32, 8);
    dim3 rg(N, 4);
    float* outf = (float*)d_out;

    // Fork side streams off the main (capture) stream.
    cudaEventRecord(evRoot, 0);
    cudaStreamWaitEvent(s1, evRoot, 0);
    cudaStreamWaitEvent(s2, evRoot, 0);

    // main: p2 transpose, then lvl0 ROI.
    {
        dim3 grid(HWs[0] / 32, CCH / 64);
        transpose_chw_to_hwc<<<grid, tb>>>(p2, offs[0], HWs[0]);
        roialign_kernel<<<rg, 128>>>(proposals, outf, 0);
    }
    // s1: p3 transpose, then lvl1 ROI.
    {
        dim3 grid(HWs[1] / 32, CCH / 64);
        transpose_chw_to_hwc<<<grid, tb, 0, s1>>>(p3, offs[1], HWs[1]);
        roialign_kernel<<<rg, 128, 0, s1>>>(proposals, outf, 1);
    }
    // s2: p4 + p5 transposes, then lvl>=2 ROI.
    {
        dim3 g4(HWs[2] / 32, CCH / 64);
        transpose_chw_to_hwc<<<g4, tb, 0, s2>>>(p4, offs[2], HWs[2]);
        dim3 g5(HWs[3] / 32, CCH / 64);
        transpose_chw_to_hwc<<<g5, tb, 0, s2>>>(p5, offs[3], HWs[3]);
        roialign_kernel<<<rg, 128, 0, s2>>>(proposals, outf, 2);
    }

    // Join side streams back into the main stream.
    cudaEventRecord(ev1, s1);
    cudaEventRecord(ev2, s2);
    cudaStreamWaitEvent(0, ev1, 0);
    cudaStreamWaitEvent(0, ev2, 0);
}

// round 7
// speedup vs baseline: 3.1488x; 1.0504x over previous
#include <cuda_runtime.h>
#include <cuda_fp16.h>
#include <math_constants.h>
#include <stdint.h>

#define CCH 256               // channels
#define NLEV 4

// Transposed scratch (HW, C) for all 4 pyramid levels, fp16.
__device__ __align__(16) __half g_featT[22282240];

// ---------------------------------------------------------------------------
// Transpose (C, HW) -> (HW, C), fp32 -> fp16 (round-6 proven form).
// ---------------------------------------------------------------------------
__global__ void transpose_chw_to_hwc(const float* __restrict__ in,
                                     size_t out_off, int HW) {
    __shared__ __half2 tile[32][33];   // [hw][channel-pair]
    const int tx = threadIdx.x;          // 0..31 -> hw within tile
    const int ty = threadIdx.y;          // 0..7
    const int x  = blockIdx.x * 32 + tx; // HW index
    const int c0 = blockIdx.y * 64;      // channel tile base (64 channels)

#pragma unroll
    for (int j = 0; j < 32; j += 8) {
        const int k = ty + j;            // channel-pair index 0..31
        const float f0 = in[(size_t)(c0 + 2 * k + 0) * HW + x];
        const float f1 = in[(size_t)(c0 + 2 * k + 1) * HW + x];
        tile[tx][k] = __floats2half2_rn(f0, f1);
    }
    __syncthreads();

    const int xo = blockIdx.x * 32;
#pragma unroll
    for (int r0 = 0; r0 < 32; r0 += 8) {
        const int r = r0 + ty;           // hw row within tile
        *reinterpret_cast<__half2*>(
            &g_featT[out_off + (size_t)(xo + r) * CCH + c0 + 2 * tx]) =
            tile[r][tx];
    }
}

// ---------------------------------------------------------------------------
// ROIAlign kernel, per-level gated, half2 interpolation path.
// Grid (N, 4): blockIdx.x = proposal, blockIdx.y = 64-channel chunk.
// Setup: 196 samples' corner offsets (uint4) + bilinear weights (4x half2
// splats packed in uint4) precomputed into smem. Hot loop: 2 LDS.128 +
// 4 LDG.128 + 16 HFMA2 + 4 HMAX2 per sample per thread (8 channels).
// target_lvl: 0 -> lvl==0, 1 -> lvl==1, 2 -> lvl>=2.
// ---------------------------------------------------------------------------
__global__ __launch_bounds__(128) void roialign_kernel(
    const float* __restrict__ proposals,
    float* __restrict__ out,
    int target_lvl) {

    __shared__ float sOut[64 * 49];    // 12544 B
    __shared__ uint4 s_off[196];       // corner element-offsets (a,b,c,d)
    __shared__ uint4 s_wt [196];       // 4 half2 weight splats (wa,wb,wc,wd)

    const int n     = blockIdx.x;
    const int chunk = blockIdx.y;     // 0..3 -> channels chunk*64 .. +63
    const int tid   = threadIdx.x;
    const int g     = tid & 7;        // channel group (8 channels each)
    const int p     = tid >> 3;       // pixel slice 0..15

    // --- per-proposal setup (uniform across block) ---
    const float px1 = proposals[n * 4 + 0];
    const float py1 = proposals[n * 4 + 1];
    const float px2 = proposals[n * 4 + 2];
    const float py2 = proposals[n * 4 + 3];

    const float pw = px2 - px1;
    const float ph = py2 - py1;
    const float lf = floorf(2.0f + log2f(sqrtf(pw * ph) / 224.0f));
    int lvl = (int)lf;
    lvl = lvl < 0 ? 0 : (lvl > 3 ? 3 : lvl);

    // Level gate (uniform per block, before any __syncthreads).
    const int lvlClass = lvl >= 2 ? 2 : lvl;
    if (lvlClass != target_lvl) return;

    const float scales[NLEV] = {0.25f, 0.125f, 0.0625f, 0.03125f};
    const int   sizes [NLEV] = {256, 128, 64, 32};
    const size_t offs [NLEV] = {0, 16777216, 16777216 + 4194304,
                                16777216 + 4194304 + 1048576};

    const float sc  = scales[lvl];
    const int   Sz  = sizes[lvl];
    const float bx1 = px1 * sc, by1 = py1 * sc;
    const float bx2 = px2 * sc, by2 = py2 * sc;
    const float w_unit = ((bx2 - bx1) / 7.0f) * 0.5f;
    const float h_unit = ((by2 - by1) / 7.0f) * 0.5f;

    // --- per-sample precompute: offsets + half2-splat weights ---
    for (int s = tid; s < 196; s += 128) {
        const int gy = s / 14;
        const int gx = s - gy * 14;

        const float x  = bx1 + ((float)gx + 0.5f) * w_unit;
        const float y  = by1 + ((float)gy + 0.5f) * h_unit;
        const int   xf = (int)floorf(x);
        const int   yf = (int)floorf(y);
        int x0 = xf;     x0 = x0 < 0 ? 0 : (x0 > Sz - 1 ? Sz - 1 : x0);
        int x1 = xf + 1; x1 = x1 < 0 ? 0 : (x1 > Sz - 1 ? Sz - 1 : x1);
        int y0 = yf;     y0 = y0 < 0 ? 0 : (y0 > Sz - 1 ? Sz - 1 : y0);
        int y1 = yf + 1; y1 = y1 < 0 ? 0 : (y1 > Sz - 1 ? Sz - 1 : y1);

        const float dx0 = x - (float)x0;   // (x - x0f)
        const float dx1 = (float)x1 - x;   // (x1f - x)
        const float dy0 = y - (float)y0;   // (y - y0f)
        const float dy1 = (float)y1 - y;   // (y1f - y)

        uint4 off;
        off.x = (unsigned)((y0 * Sz + x0) * CCH);   // la
        off.y = (unsigned)((y1 * Sz + x0) * CCH);   // lb
        off.z = (unsigned)((y0 * Sz + x1) * CCH);   // lc
        off.w = (unsigned)((y1 * Sz + x1) * CCH);   // ld
        s_off[s] = off;

        const __half2 wa = __float2half2_rn(dx1 * dy1);
        const __half2 wb = __float2half2_rn(dx1 * dy0);
        const __half2 wc = __float2half2_rn(dx0 * dy1);
        const __half2 wd = __float2half2_rn(dx0 * dy0);
        uint4 wt;
        wt.x = *reinterpret_cast<const unsigned*>(&wa);
        wt.y = *reinterpret_cast<const unsigned*>(&wb);
        wt.z = *reinterpret_cast<const unsigned*>(&wc);
        wt.w = *reinterpret_cast<const unsigned*>(&wd);
        s_wt[s] = wt;
    }
    __syncthreads();

    const int cb = g * 8;                    // channel within chunk (0..56)
    const int cg = chunk * 64 + cb;          // global channel
    const __half* __restrict__ fbase = g_featT + offs[lvl] + cg;

    const __half2 neginf2 = __float2half2_rn(-CUDART_INF_F);

    for (int pix = p; pix < 49; pix += 16) {
        const int oy = pix / 7;
        const int ox = pix - oy * 7;
        const int sTL = (oy * 2) * 14 + ox * 2;

        __half2 vmax2[4];
#pragma unroll
        for (int q = 0; q < 4; ++q) vmax2[q] = neginf2;

        const int sids[4] = {sTL, sTL + 1, sTL + 14, sTL + 15};
#pragma unroll
        for (int si = 0; si < 4; ++si) {
            const int s = sids[si];
            const uint4 off = s_off[s];
            const uint4 wt  = s_wt[s];
            const __half2 wa2 = *reinterpret_cast<const __half2*>(&wt.x);
            const __half2 wb2 = *reinterpret_cast<const __half2*>(&wt.y);
            const __half2 wc2 = *reinterpret_cast<const __half2*>(&wt.z);
            const __half2 wd2 = *reinterpret_cast<const __half2*>(&wt.w);

            const uint4 ua = *reinterpret_cast<const uint4*>(fbase + off.x);
            const uint4 ub = *reinterpret_cast<const uint4*>(fbase + off.y);
            const uint4 uc = *reinterpret_cast<const uint4*>(fbase + off.z);
            const uint4 ud = *reinterpret_cast<const uint4*>(fbase + off.w);

            const __half2* ha = reinterpret_cast<const __half2*>(&ua);
            const __half2* hb = reinterpret_cast<const __half2*>(&ub);
            const __half2* hc = reinterpret_cast<const __half2*>(&uc);
            const __half2* hd = reinterpret_cast<const __half2*>(&ud);

#pragma unroll
            for (int q = 0; q < 4; ++q) {
                __half2 acc = __hmul2(wa2, ha[q]);
                acc = __hfma2(wb2, hb[q], acc);
                acc = __hfma2(wc2, hc[q], acc);
                acc = __hfma2(wd2, hd[q], acc);
                vmax2[q] = __hmax2(vmax2[q], acc);
            }
        }

        // Stage in smem (fp32), layout (64, 49).
#pragma unroll
        for (int q = 0; q < 4; ++q) {
            const float2 f = __half22float2(vmax2[q]);
            sOut[(cb + 2 * q + 0) * 49 + pix] = f.x;
            sOut[(cb + 2 * q + 1) * 49 + pix] = f.y;
        }
    }

    __syncthreads();

    // Coalesced flush: 64*49 = 3136 floats = 784 float4.
    float4* __restrict__ o4 = reinterpret_cast<float4*>(
        out + (size_t)n * 12544 + (size_t)chunk * 3136);
    const float4* __restrict__ s4 = reinterpret_cast<const float4*>(sOut);
    for (int k = tid; k < 784; k += 128) {
        o4[k] = s4[k];
    }
}

// ---------------------------------------------------------------------------
// Launch graph (round-6 proven):
//   main: T(p2) -> ROI(lvl0)
//   s1:   T(p3) -> ROI(lvl1)
//   s2:   T(p4) -> T(p5) -> ROI(lvl>=2)
// ---------------------------------------------------------------------------
extern "C" void kernel_launch(void* const* d_in, const int* in_sizes, int n_in,
                              void* d_out, int out_size) {
    const float* p2 = (const float*)d_in[0];  // (1,256,256,256)
    const float* p3 = (const float*)d_in[1];  // (1,256,128,128)
    const float* p4 = (const float*)d_in[2];  // (1,256,64,64)
    const float* p5 = (const float*)d_in[3];  // (1,256,32,32)
    const float* proposals = (const float*)d_in[4];
    const int N = in_sizes[4] / 4;

    const int    HWs [NLEV] = {65536, 16384, 4096, 1024};
    const size_t offs[NLEV] = {0, 16777216, 16777216 + 4194304,
                               16777216 + 4194304 + 1048576};

    static cudaStream_t s1 = nullptr, s2 = nullptr;
    static cudaEvent_t evRoot = nullptr, ev1 = nullptr, ev2 = nullptr;
    if (s1 == nullptr) {
        cudaStreamCreateWithFlags(&s1, cudaStreamNonBlocking);
        cudaStreamCreateWithFlags(&s2, cudaStreamNonBlocking);
        cudaEventCreateWithFlags(&evRoot, cudaEventDisableTiming);
        cudaEventCreateWithFlags(&ev1, cudaEventDisableTiming);
        cudaEventCreateWithFlags(&ev2, cudaEventDisableTiming);
    }

    dim3 tb(32, 8);
    dim3 rg(N, 4);
    float* outf = (float*)d_out;

    // Fork side streams off the main (capture) stream.
    cudaEventRecord(evRoot, 0);
    cudaStreamWaitEvent(s1, evRoot, 0);
    cudaStreamWaitEvent(s2, evRoot, 0);

    // main: p2 transpose, then lvl0 ROI.
    {
        dim3 grid(HWs[0] / 32, CCH / 64);
        transpose_chw_to_hwc<<<grid, tb>>>(p2, offs[0], HWs[0]);
        roialign_kernel<<<rg, 128>>>(proposals, outf, 0);
    }
    // s1: p3 transpose, then lvl1 ROI.
    {
        dim3 grid(HWs[1] / 32, CCH / 64);
        transpose_chw_to_hwc<<<grid, tb, 0, s1>>>(p3, offs[1], HWs[1]);
        roialign_kernel<<<rg, 128, 0, s1>>>(proposals, outf, 1);
    }
    // s2: p4 + p5 transposes, then lvl>=2 ROI.
    {
        dim3 g4(HWs[2] / 32, CCH / 64);
        transpose_chw_to_hwc<<<g4, tb, 0, s2>>>(p4, offs[2], HWs[2]);
        dim3 g5(HWs[3] / 32, CCH / 64);
        transpose_chw_to_hwc<<<g5, tb, 0, s2>>>(p5, offs[3], HWs[3]);
        roialign_kernel<<<rg, 128, 0, s2>>>(proposals, outf, 2);
    }

    // Join side streams back into the main stream.
    cudaEventRecord(ev1, s1);
    cudaEventRecord(ev2, s2);
    cudaStreamWaitEvent(0, ev1, 0);
    cudaStreamWaitEvent(0, ev2, 0);
}

// round 8
// speedup vs baseline: 3.2612x; 1.0357x over previous
#include <cuda_runtime.h>
#include <cuda_fp16.h>
#include <math_constants.h>
#include <stdint.h>

#define CCH 256               // channels
#define NLEV 4

// Transposed scratch (HW, C) for all 4 pyramid levels, fp16.
__device__ __align__(16) __half g_featT[22282240];

// ---------------------------------------------------------------------------
// Transpose (C, HW) -> (HW, C), fp32 -> fp16 (proven form).
// ---------------------------------------------------------------------------
__global__ void transpose_chw_to_hwc(const float* __restrict__ in,
                                     size_t out_off, int HW) {
    __shared__ __half2 tile[32][33];   // [hw][channel-pair]
    const int tx = threadIdx.x;          // 0..31 -> hw within tile
    const int ty = threadIdx.y;          // 0..7
    const int x  = blockIdx.x * 32 + tx; // HW index
    const int c0 = blockIdx.y * 64;      // channel tile base (64 channels)

#pragma unroll
    for (int j = 0; j < 32; j += 8) {
        const int k = ty + j;            // channel-pair index 0..31
        const float f0 = in[(size_t)(c0 + 2 * k + 0) * HW + x];
        const float f1 = in[(size_t)(c0 + 2 * k + 1) * HW + x];
        tile[tx][k] = __floats2half2_rn(f0, f1);
    }
    __syncthreads();

    const int xo = blockIdx.x * 32;
#pragma unroll
    for (int r0 = 0; r0 < 32; r0 += 8) {
        const int r = r0 + ty;           // hw row within tile
        *reinterpret_cast<__half2*>(
            &g_featT[out_off + (size_t)(xo + r) * CCH + c0 + 2 * tx]) =
            tile[r][tx];
    }
}

// ---------------------------------------------------------------------------
// Per-sample accumulate: 4 corner uint4 (8 halves each) * half2 weights.
// ---------------------------------------------------------------------------
__device__ __forceinline__ void accum_sample(
    const uint4& ua, const uint4& ub, const uint4& uc, const uint4& ud,
    const uint4& wt, __half2 vmax2[4]) {
    const __half2 wa2 = *reinterpret_cast<const __half2*>(&wt.x);
    const __half2 wb2 = *reinterpret_cast<const __half2*>(&wt.y);
    const __half2 wc2 = *reinterpret_cast<const __half2*>(&wt.z);
    const __half2 wd2 = *reinterpret_cast<const __half2*>(&wt.w);
    const __half2* ha = reinterpret_cast<const __half2*>(&ua);
    const __half2* hb = reinterpret_cast<const __half2*>(&ub);
    const __half2* hc = reinterpret_cast<const __half2*>(&uc);
    const __half2* hd = reinterpret_cast<const __half2*>(&ud);
#pragma unroll
    for (int q = 0; q < 4; ++q) {
        __half2 acc = __hmul2(wa2, ha[q]);
        acc = __hfma2(wb2, hb[q], acc);
        acc = __hfma2(wc2, hc[q], acc);
        acc = __hfma2(wd2, hd[q], acc);
        vmax2[q] = __hmax2(vmax2[q], acc);
    }
}

// ---------------------------------------------------------------------------
// ROIAlign kernel, per-level gated, half2 path, MLP-8 load batching.
// Grid (N, 4): blockIdx.x = proposal, blockIdx.y = 64-channel chunk.
// target_lvl: 0 -> lvl==0, 1 -> lvl==1, 2 -> lvl>=2.
// ---------------------------------------------------------------------------
__global__ __launch_bounds__(128) void roialign_kernel(
    const float* __restrict__ proposals,
    float* __restrict__ out,
    int target_lvl) {

    __shared__ float sOut[64 * 49];    // 12544 B
    __shared__ uint4 s_off[196];       // corner element-offsets (a,b,c,d)
    __shared__ uint4 s_wt [196];       // 4 half2 weight splats (wa,wb,wc,wd)

    const int n     = blockIdx.x;
    const int chunk = blockIdx.y;     // 0..3 -> channels chunk*64 .. +63
    const int tid   = threadIdx.x;
    const int g     = tid & 7;        // channel group (8 channels each)
    const int p     = tid >> 3;       // pixel slice 0..15

    // --- per-proposal setup (uniform across block) ---
    const float px1 = proposals[n * 4 + 0];
    const float py1 = proposals[n * 4 + 1];
    const float px2 = proposals[n * 4 + 2];
    const float py2 = proposals[n * 4 + 3];

    const float pw = px2 - px1;
    const float ph = py2 - py1;
    const float lf = floorf(2.0f + log2f(sqrtf(pw * ph) / 224.0f));
    int lvl = (int)lf;
    lvl = lvl < 0 ? 0 : (lvl > 3 ? 3 : lvl);

    // Level gate (uniform per block, before any __syncthreads).
    const int lvlClass = lvl >= 2 ? 2 : lvl;
    if (lvlClass != target_lvl) return;

    const float scales[NLEV] = {0.25f, 0.125f, 0.0625f, 0.03125f};
    const int   sizes [NLEV] = {256, 128, 64, 32};
    const size_t offs [NLEV] = {0, 16777216, 16777216 + 4194304,
                                16777216 + 4194304 + 1048576};

    const float sc  = scales[lvl];
    const int   Sz  = sizes[lvl];
    const float bx1 = px1 * sc, by1 = py1 * sc;
    const float bx2 = px2 * sc, by2 = py2 * sc;
    const float w_unit = ((bx2 - bx1) / 7.0f) * 0.5f;
    const float h_unit = ((by2 - by1) / 7.0f) * 0.5f;

    // --- per-sample precompute: offsets + half2-splat weights ---
    for (int s = tid; s < 196; s += 128) {
        const int gy = s / 14;
        const int gx = s - gy * 14;

        const float x  = bx1 + ((float)gx + 0.5f) * w_unit;
        const float y  = by1 + ((float)gy + 0.5f) * h_unit;
        const int   xf = (int)floorf(x);
        const int   yf = (int)floorf(y);
        int x0 = xf;     x0 = x0 < 0 ? 0 : (x0 > Sz - 1 ? Sz - 1 : x0);
        int x1 = xf + 1; x1 = x1 < 0 ? 0 : (x1 > Sz - 1 ? Sz - 1 : x1);
        int y0 = yf;     y0 = y0 < 0 ? 0 : (y0 > Sz - 1 ? Sz - 1 : y0);
        int y1 = yf + 1; y1 = y1 < 0 ? 0 : (y1 > Sz - 1 ? Sz - 1 : y1);

        const float dx0 = x - (float)x0;   // (x - x0f)
        const float dx1 = (float)x1 - x;   // (x1f - x)
        const float dy0 = y - (float)y0;   // (y - y0f)
        const float dy1 = (float)y1 - y;   // (y1f - y)

        uint4 off;
        off.x = (unsigned)((y0 * Sz + x0) * CCH);   // la
        off.y = (unsigned)((y1 * Sz + x0) * CCH);   // lb
        off.z = (unsigned)((y0 * Sz + x1) * CCH);   // lc
        off.w = (unsigned)((y1 * Sz + x1) * CCH);   // ld
        s_off[s] = off;

        const __half2 wa = __float2half2_rn(dx1 * dy1);
        const __half2 wb = __float2half2_rn(dx1 * dy0);
        const __half2 wc = __float2half2_rn(dx0 * dy1);
        const __half2 wd = __float2half2_rn(dx0 * dy0);
        uint4 wt;
        wt.x = *reinterpret_cast<const unsigned*>(&wa);
        wt.y = *reinterpret_cast<const unsigned*>(&wb);
        wt.z = *reinterpret_cast<const unsigned*>(&wc);
        wt.w = *reinterpret_cast<const unsigned*>(&wd);
        s_wt[s] = wt;
    }
    __syncthreads();

    const int cb = g * 8;                    // channel within chunk (0..56)
    const int cg = chunk * 64 + cb;          // global channel
    const __half* __restrict__ fbase = g_featT + offs[lvl] + cg;

    const __half2 neginf2 = __float2half2_rn(-CUDART_INF_F);

    for (int pix = p; pix < 49; pix += 16) {
        const int oy = pix / 7;
        const int ox = pix - oy * 7;
        const int sTL = (oy * 2) * 14 + ox * 2;

        __half2 vmax2[4];
#pragma unroll
        for (int q = 0; q < 4; ++q) vmax2[q] = neginf2;

        const int sids[4] = {sTL, sTL + 1, sTL + 14, sTL + 15};

        // Two sample-pairs; within a pair, ALL 8 corner loads are issued
        // before any consumption -> MLP >= 8 per thread.
#pragma unroll
        for (int sb = 0; sb < 2; ++sb) {
            const int sA = sids[2 * sb + 0];
            const int sB = sids[2 * sb + 1];
            const uint4 offA = s_off[sA];
            const uint4 offB = s_off[sB];
            const uint4 wtA  = s_wt[sA];
            const uint4 wtB  = s_wt[sB];

            const uint4 a0 = *reinterpret_cast<const uint4*>(fbase + offA.x);
            const uint4 b0 = *reinterpret_cast<const uint4*>(fbase + offA.y);
            const uint4 c0 = *reinterpret_cast<const uint4*>(fbase + offA.z);
            const uint4 d0 = *reinterpret_cast<const uint4*>(fbase + offA.w);
            const uint4 a1 = *reinterpret_cast<const uint4*>(fbase + offB.x);
            const uint4 b1 = *reinterpret_cast<const uint4*>(fbase + offB.y);
            const uint4 c1 = *reinterpret_cast<const uint4*>(fbase + offB.z);
            const uint4 d1 = *reinterpret_cast<const uint4*>(fbase + offB.w);

            accum_sample(a0, b0, c0, d0, wtA, vmax2);
            accum_sample(a1, b1, c1, d1, wtB, vmax2);
        }

        // Stage in smem (fp32), layout (64, 49).
#pragma unroll
        for (int q = 0; q < 4; ++q) {
            const float2 f = __half22float2(vmax2[q]);
            sOut[(cb + 2 * q + 0) * 49 + pix] = f.x;
            sOut[(cb + 2 * q + 1) * 49 + pix] = f.y;
        }
    }

    __syncthreads();

    // Coalesced flush: 64*49 = 3136 floats = 784 float4.
    float4* __restrict__ o4 = reinterpret_cast<float4*>(
        out + (size_t)n * 12544 + (size_t)chunk * 3136);
    const float4* __restrict__ s4 = reinterpret_cast<const float4*>(sOut);
    for (int k = tid; k < 784; k += 128) {
        o4[k] = s4[k];
    }
}

// ---------------------------------------------------------------------------
// Launch graph (proven):
//   main: T(p2) -> ROI(lvl0)
//   s1:   T(p3) -> ROI(lvl1)
//   s2:   T(p4) -> T(p5) -> ROI(lvl>=2)
// ---------------------------------------------------------------------------
extern "C" void kernel_launch(void* const* d_in, const int* in_sizes, int n_in,
                              void* d_out, int out_size) {
    const float* p2 = (const float*)d_in[0];  // (1,256,256,256)
    const float* p3 = (const float*)d_in[1];  // (1,256,128,128)
    const float* p4 = (const float*)d_in[2];  // (1,256,64,64)
    const float* p5 = (const float*)d_in[3];  // (1,256,32,32)
    const float* proposals = (const float*)d_in[4];
    const int N = in_sizes[4] / 4;

    const int    HWs [NLEV] = {65536, 16384, 4096, 1024};
    const size_t offs[NLEV] = {0, 16777216, 16777216 + 4194304,
                               16777216 + 4194304 + 1048576};

    static cudaStream_t s1 = nullptr, s2 = nullptr;
    static cudaEvent_t evRoot = nullptr, ev1 = nullptr, ev2 = nullptr;
    if (s1 == nullptr) {
        cudaStreamCreateWithFlags(&s1, cudaStreamNonBlocking);
        cudaStreamCreateWithFlags(&s2, cudaStreamNonBlocking);
        cudaEventCreateWithFlags(&evRoot, cudaEventDisableTiming);
        cudaEventCreateWithFlags(&ev1, cudaEventDisableTiming);
        cudaEventCreateWithFlags(&ev2, cudaEventDisableTiming);
    }

    dim3 tb(32, 8);
    dim3 rg(N, 4);
    float* outf = (float*)d_out;

    // Fork side streams off the main (capture) stream.
    cudaEventRecord(evRoot, 0);
    cudaStreamWaitEvent(s1, evRoot, 0);
    cudaStreamWaitEvent(s2, evRoot, 0);

    // main: p2 transpose, then lvl0 ROI.
    {
        dim3 grid(HWs[0] / 32, CCH / 64);
        transpose_chw_to_hwc<<<grid, tb>>>(p2, offs[0], HWs[0]);
        roialign_kernel<<<rg, 128>>>(proposals, outf, 0);
    }
    // s1: p3 transpose, then lvl1 ROI.
    {
        dim3 grid(HWs[1] / 32, CCH / 64);
        transpose_chw_to_hwc<<<grid, tb, 0, s1>>>(p3, offs[1], HWs[1]);
        roialign_kernel<<<rg, 128, 0, s1>>>(proposals, outf, 1);
    }
    // s2: p4 + p5 transposes, then lvl>=2 ROI.
    {
        dim3 g4(HWs[2] / 32, CCH / 64);
        transpose_chw_to_hwc<<<g4, tb, 0, s2>>>(p4, offs[2], HWs[2]);
        dim3 g5(HWs[3] / 32, CCH / 64);
        transpose_chw_to_hwc<<<g5, tb, 0, s2>>>(p5, offs[3], HWs[3]);
        roialign_kernel<<<rg, 128, 0, s2>>>(proposals, outf, 2);
    }

    // Join side streams back into the main stream.
    cudaEventRecord(ev1, s1);
    cudaEventRecord(ev2, s2);
    cudaStreamWaitEvent(0, ev1, 0);
    cudaStreamWaitEvent(0, ev2, 0);
}